// round 3
// baseline (speedup 1.0000x reference)
#include <cuda_runtime.h>

// Problem constants
#define B_  2
#define T_  2048
#define C_  1024
#define H_  16
#define HD_ 64

// Scratch (allocation-free rule: __device__ globals)
static __device__ float g_Q[B_*T_*C_];
static __device__ float g_K[B_*T_*C_];
static __device__ float g_V[B_*T_*C_];
static __device__ float g_Y[B_*T_*C_];

// ---------------------------------------------------------------------------
// GEMM + bias: out[M,N] = X[M,K] @ W[K,N] + bias[N]
// 128x128 block tile, 256 threads, 8x8 per thread, BK=8.
// M=4096, N=1024, K=1024 -> all dims divisible, no edge handling.
// ---------------------------------------------------------------------------
#define GM 128
#define GN 128
#define GK 8
#define GM_PAD 132   // pad As rows: 132*4B = 528B, 16B-aligned, conflict-free stores

__global__ __launch_bounds__(256)
void gemm_bias_kernel(const float* __restrict__ X,
                      const float* __restrict__ W,
                      const float* __restrict__ bias,
                      float* __restrict__ out,
                      int M, int N, int K)
{
    __shared__ float As[GK][GM_PAD];  // transposed A tile: As[k][m]
    __shared__ float Bs[GK][GN];      // Bs[k][n]

    const int t  = threadIdx.x;
    const int tx = t & 15;   // 0..15, col group (8 cols each)
    const int ty = t >> 4;   // 0..15, row group (8 rows each)
    const int row0 = blockIdx.y * GM;
    const int col0 = blockIdx.x * GN;

    // A tile load: 128 rows x 8 k = 256 float4; thread -> row=t>>1, k=(t&1)*4
    const int arow = t >> 1;
    const int acol = (t & 1) * 4;
    // B tile load: 8 k x 128 n = 256 float4; thread -> k=t>>5, n=(t&31)*4
    const int brow = t >> 5;
    const int bcol = (t & 31) * 4;

    float acc[8][8] = {};

    for (int k0 = 0; k0 < K; k0 += GK) {
        const float4 av = *(const float4*)&X[(size_t)(row0 + arow) * K + k0 + acol];
        As[acol + 0][arow] = av.x;
        As[acol + 1][arow] = av.y;
        As[acol + 2][arow] = av.z;
        As[acol + 3][arow] = av.w;
        *(float4*)&Bs[brow][bcol] =
            *(const float4*)&W[(size_t)(k0 + brow) * N + col0 + bcol];
        __syncthreads();

        #pragma unroll
        for (int kk = 0; kk < GK; kk++) {
            float a[8], b[8];
            *(float4*)&a[0] = *(float4*)&As[kk][ty * 8];
            *(float4*)&a[4] = *(float4*)&As[kk][ty * 8 + 4];
            *(float4*)&b[0] = *(float4*)&Bs[kk][tx * 8];
            *(float4*)&b[4] = *(float4*)&Bs[kk][tx * 8 + 4];
            #pragma unroll
            for (int i = 0; i < 8; i++)
                #pragma unroll
                for (int j = 0; j < 8; j++)
                    acc[i][j] += a[i] * b[j];
        }
        __syncthreads();
    }

    #pragma unroll
    for (int i = 0; i < 8; i++) {
        const int r = row0 + ty * 8 + i;
        #pragma unroll
        for (int j = 0; j < 8; j += 4) {
            const int c = col0 + tx * 8 + j;
            float4 o;
            o.x = acc[i][j + 0] + bias[c + 0];
            o.y = acc[i][j + 1] + bias[c + 1];
            o.z = acc[i][j + 2] + bias[c + 2];
            o.w = acc[i][j + 3] + bias[c + 3];
            *(float4*)&out[(size_t)r * N + c] = o;
        }
    }
}

// ---------------------------------------------------------------------------
// Flash-attention-style causal attention, fp32.
// Grid: (T/64, H, B). Block: 256 threads (16x16), 4x4 per thread.
// Q tile 64x64 resident; loop K/V tiles of 64 up to the diagonal with
// online softmax; P round-trips through smem (reusing the K buffer).
// smem: Qs[64][64] + Ks[64][65] + Vs[64][64] = 49408 B (dynamic, opt-in).
// ---------------------------------------------------------------------------
#define BR 64
#define BC 64

__global__ __launch_bounds__(256)
void attn_kernel(const float* __restrict__ Q,
                 const float* __restrict__ K,
                 const float* __restrict__ V,
                 float* __restrict__ Y)
{
    extern __shared__ float sm[];
    float* Qs = sm;                       // [64][64]
    float* Ks = sm + 64 * 64;             // [64][65]  (reused for P)
    float* Vs = sm + 64 * 64 + 64 * 65;   // [64][64]
#define QS(r, d) Qs[(r) * 64 + (d)]
#define KS(r, d) Ks[(r) * 65 + (d)]
#define VS(r, d) Vs[(r) * 64 + (d)]

    const int qt = blockIdx.x;
    const int h  = blockIdx.y;
    const int b  = blockIdx.z;
    const int t  = threadIdx.x;
    const int tx = t & 15;
    const int ty = t >> 4;
    const float scale = 0.125f;  // 1/sqrt(64)

    const size_t base = (size_t)b * T_ * C_ + (size_t)h * HD_;

    // Load Q tile (coalesced over d)
    for (int i = t; i < BR * HD_; i += 256) {
        const int r = i >> 6, d = i & 63;
        QS(r, d) = Q[base + (size_t)(qt * BR + r) * C_ + d];
    }

    float acc[4][4] = {};
    float m_i[4], l_i[4];
    #pragma unroll
    for (int i = 0; i < 4; i++) { m_i[i] = -1e30f; l_i[i] = 0.f; }

    for (int kt = 0; kt <= qt; kt++) {
        // Load K and V tiles
        for (int i = t; i < BC * HD_; i += 256) {
            const int r = i >> 6, d = i & 63;
            KS(r, d) = K[base + (size_t)(kt * BC + r) * C_ + d];
            VS(r, d) = V[base + (size_t)(kt * BC + r) * C_ + d];
        }
        __syncthreads();   // also covers Qs on first iteration

        // S = Q @ K^T (4x4 per thread)
        float s[4][4] = {};
        #pragma unroll
        for (int d = 0; d < HD_; d++) {
            float a[4], kk[4];
            #pragma unroll
            for (int i = 0; i < 4; i++) a[i]  = QS(ty * 4 + i, d);
            #pragma unroll
            for (int j = 0; j < 4; j++) kk[j] = KS(tx * 4 + j, d);
            #pragma unroll
            for (int i = 0; i < 4; i++)
                #pragma unroll
                for (int j = 0; j < 4; j++)
                    s[i][j] += a[i] * kk[j];
        }

        // Scale + causal mask (diagonal tile only)
        #pragma unroll
        for (int i = 0; i < 4; i++)
            #pragma unroll
            for (int j = 0; j < 4; j++) {
                s[i][j] *= scale;
                if (kt == qt && (tx * 4 + j) > (ty * 4 + i)) s[i][j] = -1e30f;
            }

        // Online softmax (row reduce across the 16 tx lanes)
        float p[4][4];
        #pragma unroll
        for (int i = 0; i < 4; i++) {
            float mx = s[i][0];
            #pragma unroll
            for (int j = 1; j < 4; j++) mx = fmaxf(mx, s[i][j]);
            #pragma unroll
            for (int off = 8; off >= 1; off >>= 1)
                mx = fmaxf(mx, __shfl_xor_sync(0xffffffffu, mx, off, 16));
            const float mnew = fmaxf(m_i[i], mx);

            float rs = 0.f;
            #pragma unroll
            for (int j = 0; j < 4; j++) {
                p[i][j] = __expf(s[i][j] - mnew);
                rs += p[i][j];
            }
            #pragma unroll
            for (int off = 8; off >= 1; off >>= 1)
                rs += __shfl_xor_sync(0xffffffffu, rs, off, 16);

            const float corr = __expf(m_i[i] - mnew);
            l_i[i] = l_i[i] * corr + rs;
            m_i[i] = mnew;
            #pragma unroll
            for (int dj = 0; dj < 4; dj++) acc[i][dj] *= corr;
        }

        __syncthreads();  // everyone done reading Ks as K
        // Stash P into the K buffer
        #pragma unroll
        for (int i = 0; i < 4; i++)
            #pragma unroll
            for (int j = 0; j < 4; j++)
                KS(ty * 4 + i, tx * 4 + j) = p[i][j];
        __syncthreads();

        // O += P @ V
        #pragma unroll
        for (int j = 0; j < BC; j++) {
            float pv[4], vv[4];
            #pragma unroll
            for (int i = 0; i < 4; i++)  pv[i]  = KS(ty * 4 + i, j);
            #pragma unroll
            for (int dj = 0; dj < 4; dj++) vv[dj] = VS(j, tx * 4 + dj);
            #pragma unroll
            for (int i = 0; i < 4; i++)
                #pragma unroll
                for (int dj = 0; dj < 4; dj++)
                    acc[i][dj] += pv[i] * vv[dj];
        }
        __syncthreads();  // before overwriting K/V next iteration
    }

    // Normalize and write out
    #pragma unroll
    for (int i = 0; i < 4; i++) {
        const float inv = 1.f / l_i[i];
        const int qrow = qt * BR + ty * 4 + i;
        #pragma unroll
        for (int dj = 0; dj < 4; dj++)
            Y[base + (size_t)qrow * C_ + tx * 4 + dj] = acc[i][dj] * inv;
    }
#undef QS
#undef KS
#undef VS
}

// ---------------------------------------------------------------------------
// Launch
// ---------------------------------------------------------------------------
extern "C" void kernel_launch(void* const* d_in, const int* in_sizes, int n_in,
                              void* d_out, int out_size)
{
    const float* query = (const float*)d_in[0];
    const float* key_  = (const float*)d_in[1];
    const float* value = (const float*)d_in[2];
    // d_in[3] = att_mask (constant tril) — causal masking handled analytically
    const float* Wq = (const float*)d_in[4];
    const float* bq = (const float*)d_in[5];
    const float* Wk = (const float*)d_in[6];
    const float* bk = (const float*)d_in[7];
    const float* Wv = (const float*)d_in[8];
    const float* bv = (const float*)d_in[9];
    const float* Wp = (const float*)d_in[10];
    const float* bp = (const float*)d_in[11];
    float* out = (float*)d_out;

    float *Qb, *Kb, *Vb, *Yb;
    cudaGetSymbolAddress((void**)&Qb, g_Q);
    cudaGetSymbolAddress((void**)&Kb, g_K);
    cudaGetSymbolAddress((void**)&Vb, g_V);
    cudaGetSymbolAddress((void**)&Yb, g_Y);

    const int M = B_ * T_;   // 4096
    const int N = C_;        // 1024
    const int K = C_;        // 1024

    dim3 gblk(256);
    dim3 ggrid(N / GN, M / GM);   // 8 x 32 = 256 blocks

    // QKV projections
    gemm_bias_kernel<<<ggrid, gblk>>>(query, Wq, bq, Qb, M, N, K);
    gemm_bias_kernel<<<ggrid, gblk>>>(key_,  Wk, bk, Kb, M, N, K);
    gemm_bias_kernel<<<ggrid, gblk>>>(value, Wv, bv, Vb, M, N, K);

    // Attention
    const int smem_bytes = (64 * 64 + 64 * 65 + 64 * 64) * (int)sizeof(float); // 49408
    cudaFuncSetAttribute(attn_kernel, cudaFuncAttributeMaxDynamicSharedMemorySize, smem_bytes);
    dim3 agrid(T_ / BR, H_, B_);
    attn_kernel<<<agrid, 256, smem_bytes>>>(Qb, Kb, Vb, Yb);

    // Output projection
    gemm_bias_kernel<<<ggrid, gblk>>>(Yb, Wp, bp, out, M, N, K);
}

// round 11
// speedup vs baseline: 1.5139x; 1.5139x over previous
#include <cuda_runtime.h>
#include <cuda_bf16.h>
#include <cstdint>

// Problem constants
#define B_  2
#define T_  2048
#define C_  1024
#define H_  16
#define HD_ 64
#define M_  (B_*T_)   // 4096
#define N_  C_        // 1024
#define K_  C_        // 1024

// Scratch (allocation-free rule: __device__ globals)
static __device__ float g_Q[M_*C_];
static __device__ float g_K[M_*C_];
static __device__ float g_V[M_*C_];
static __device__ float g_Y[M_*C_];
static __device__ __nv_bfloat16 g_Ahi[M_*K_];
static __device__ __nv_bfloat16 g_Alo[M_*K_];
static __device__ __nv_bfloat16 g_Bhi[N_*K_];   // W^T hi  [N,K]
static __device__ __nv_bfloat16 g_Blo[N_*K_];   // W^T lo  [N,K]

// ---------------------------------------------------------------------------
// PTX helpers (base sm_103-compatible: mma.sync / ldmatrix / cp.async only)
// ---------------------------------------------------------------------------
__device__ __forceinline__ uint32_t smem_u32(const void* p) {
    uint32_t a;
    asm("{ .reg .u64 t; cvta.to.shared.u64 t, %1; cvt.u32.u64 %0, t; }"
        : "=r"(a) : "l"(p));
    return a;
}

#define CP_ASYNC16(s, g) \
    asm volatile("cp.async.cg.shared.global [%0], [%1], 16;" :: "r"(s), "l"(g))
#define CP_COMMIT() asm volatile("cp.async.commit_group;" ::: "memory")
#define CP_WAIT0()  asm volatile("cp.async.wait_group 0;" ::: "memory")
#define CP_WAIT1()  asm volatile("cp.async.wait_group 1;" ::: "memory")

__device__ __forceinline__ void ldsm_x4(uint32_t& r0, uint32_t& r1,
                                        uint32_t& r2, uint32_t& r3, uint32_t a) {
    asm volatile("ldmatrix.sync.aligned.m8n8.x4.shared.b16 {%0,%1,%2,%3}, [%4];"
                 : "=r"(r0), "=r"(r1), "=r"(r2), "=r"(r3) : "r"(a));
}

__device__ __forceinline__ void mma_bf16(float* c, uint32_t a0, uint32_t a1,
                                         uint32_t a2, uint32_t a3,
                                         uint32_t b0, uint32_t b1) {
    asm volatile(
        "mma.sync.aligned.m16n8k16.row.col.f32.bf16.bf16.f32 "
        "{%0,%1,%2,%3}, {%4,%5,%6,%7}, {%8,%9}, {%0,%1,%2,%3};"
        : "+f"(c[0]), "+f"(c[1]), "+f"(c[2]), "+f"(c[3])
        : "r"(a0), "r"(a1), "r"(a2), "r"(a3), "r"(b0), "r"(b1));
}

// ---------------------------------------------------------------------------
// Prepass: split fp32 -> bf16 hi + lo (elementwise; X stays [M,K])
// ---------------------------------------------------------------------------
__device__ __forceinline__ uint32_t pack_bf2(__nv_bfloat16 a, __nv_bfloat16 b) {
    __nv_bfloat162 t = __halves2bfloat162(a, b);
    return *(uint32_t*)&t;
}

__global__ __launch_bounds__(256)
void splitX_kernel(const float* __restrict__ X,
                   __nv_bfloat16* __restrict__ Xhi,
                   __nv_bfloat16* __restrict__ Xlo)
{
    const int i = blockIdx.x * 256 + threadIdx.x;   // one float4 per thread
    const float4 v = ((const float4*)X)[i];
    float a[4] = {v.x, v.y, v.z, v.w};
    __nv_bfloat16 h[4], l[4];
    #pragma unroll
    for (int p = 0; p < 4; p++) {
        h[p] = __float2bfloat16(a[p]);
        l[p] = __float2bfloat16(a[p] - __bfloat162float(h[p]));
    }
    ((uint2*)Xhi)[i] = make_uint2(pack_bf2(h[0], h[1]), pack_bf2(h[2], h[3]));
    ((uint2*)Xlo)[i] = make_uint2(pack_bf2(l[0], l[1]), pack_bf2(l[2], l[3]));
}

// Prepass: W [K,N] fp32 -> W^T hi/lo bf16 [N,K] (32x32 smem transpose)
__global__ __launch_bounds__(256)
void splitWT_kernel(const float* __restrict__ W,
                    __nv_bfloat16* __restrict__ WThi,
                    __nv_bfloat16* __restrict__ WTlo)
{
    __shared__ float tile[32][33];
    const int n0 = blockIdx.x * 32, k0 = blockIdx.y * 32;
    #pragma unroll
    for (int j = 0; j < 32; j += 8)
        tile[threadIdx.y + j][threadIdx.x] =
            W[(size_t)(k0 + threadIdx.y + j) * N_ + n0 + threadIdx.x];
    __syncthreads();
    #pragma unroll
    for (int j = 0; j < 32; j += 8) {
        const float v = tile[threadIdx.x][threadIdx.y + j];
        const __nv_bfloat16 h = __float2bfloat16(v);
        const float lo = v - __bfloat162float(h);
        const size_t o = (size_t)(n0 + threadIdx.y + j) * K_ + k0 + threadIdx.x;
        WThi[o] = h;
        WTlo[o] = __float2bfloat16(lo);
    }
}

// ---------------------------------------------------------------------------
// mma.sync GEMM: out[M,N] = (Ahi+Alo)[M,K] @ (Bhi+Blo)^T[N,K] + bias
// split-bf16: Ahi*Bhi + Alo*Bhi + Ahi*Blo, fp32 accumulators.
// CTA 128x128, 8 warps (4Mx2N), warp tile 32x64, BK=32, 2-stage cp.async.
// smem rows: 32 bf16 data + 8 pad = 80B stride (conflict-free ldmatrix).
// ---------------------------------------------------------------------------
#define ROWB 80
#define TILE_BYTES (128 * ROWB)        // 10240
#define STAGE_BYTES (4 * TILE_BYTES)   // 40960: Ahi|Alo|Bhi|Blo
#define SMEM_GEMM (2 * STAGE_BYTES)    // 81920
#define NC (K_ / 32)                   // 32 k-chunks

__global__ __launch_bounds__(256, 2)
void gemm_mma_kernel(const __nv_bfloat16* __restrict__ Ahi,
                     const __nv_bfloat16* __restrict__ Alo,
                     const __nv_bfloat16* __restrict__ Bhi,
                     const __nv_bfloat16* __restrict__ Blo,
                     const float* __restrict__ bias,
                     float* __restrict__ out)
{
    extern __shared__ char smc[];
    const uint32_t sbase = smem_u32(smc);
    const int t = threadIdx.x;
    const int lane = t & 31;
    const int warp = t >> 5;
    const int wm = warp & 3;          // 0..3 (M)
    const int wn = warp >> 2;         // 0..1 (N)
    const int row0 = blockIdx.y * 128;
    const int col0 = blockIdx.x * 128;

    float acc[2][8][4];
    #pragma unroll
    for (int i = 0; i < 2; i++)
        #pragma unroll
        for (int j = 0; j < 8; j++)
            #pragma unroll
            for (int k = 0; k < 4; k++) acc[i][j][k] = 0.f;

    // Loader: per stage, 4 tiles x 512 16B-segments; 8 cp.async per thread.
    const int lr = (t >> 2);          // rows covered: t/4 and +64
    const int ls = (t & 3);           // k-seg 0..3

    // ldmatrix lane addressing (precomputed per-thread offsets)
    const int a_row = (lane & 15);                 // + wm*32 + mt*16
    const int a_koff = (lane >> 4) << 3;           // 0 or 8 (+kk)
    const int b_nrow = (((lane >> 4) & 1) << 3) + (lane & 7);  // + wn*64 + np*16
    const int b_koff = ((lane >> 3) & 1) << 3;     // 0 or 8 (+kk)

    #pragma unroll 1
    for (int c = 0; c < NC + 1; c++) {
        // Prefetch chunk c into stage c&1 (chunks 0..NC-1)
        if (c < NC) {
            const int k0 = c * 32;
            const uint32_t sb = sbase + (c & 1) * STAGE_BYTES;
            #pragma unroll
            for (int i = 0; i < 2; i++) {
                const int r = lr + i * 64;
                const uint32_t so = r * ROWB + ls * 16;
                const size_t goA = (size_t)(row0 + r) * K_ + k0 + ls * 8;
                const size_t goB = (size_t)(col0 + r) * K_ + k0 + ls * 8;
                CP_ASYNC16(sb + 0 * TILE_BYTES + so, Ahi + goA);
                CP_ASYNC16(sb + 1 * TILE_BYTES + so, Alo + goA);
                CP_ASYNC16(sb + 2 * TILE_BYTES + so, Bhi + goB);
                CP_ASYNC16(sb + 3 * TILE_BYTES + so, Blo + goB);
            }
            CP_COMMIT();
        }
        if (c == 0) continue;   // nothing to compute yet

        // Compute chunk c-1 (stage (c-1)&1); its group must be drained.
        if (c < NC) CP_WAIT1(); else CP_WAIT0();
        __syncthreads();

        const uint32_t sA  = sbase + ((c - 1) & 1) * STAGE_BYTES;
        const uint32_t sAl = sA + 1 * TILE_BYTES;
        const uint32_t sB  = sA + 2 * TILE_BYTES;
        const uint32_t sBl = sA + 3 * TILE_BYTES;

        #pragma unroll
        for (int kk = 0; kk < 32; kk += 16) {
            uint32_t a[2][4], b[4][4];
            // --- pass 1: Ahi * Bhi ---
            #pragma unroll
            for (int mt = 0; mt < 2; mt++)
                ldsm_x4(a[mt][0], a[mt][1], a[mt][2], a[mt][3],
                        sA + (wm * 32 + mt * 16 + a_row) * ROWB + (kk + a_koff) * 2);
            #pragma unroll
            for (int np = 0; np < 4; np++)
                ldsm_x4(b[np][0], b[np][1], b[np][2], b[np][3],
                        sB + (wn * 64 + np * 16 + b_nrow) * ROWB + (kk + b_koff) * 2);
            #pragma unroll
            for (int mt = 0; mt < 2; mt++)
                #pragma unroll
                for (int np = 0; np < 4; np++) {
                    mma_bf16(acc[mt][2 * np],     a[mt][0], a[mt][1], a[mt][2], a[mt][3], b[np][0], b[np][1]);
                    mma_bf16(acc[mt][2 * np + 1], a[mt][0], a[mt][1], a[mt][2], a[mt][3], b[np][2], b[np][3]);
                }
            // --- pass 2: Alo * Bhi (reuse b) ---
            #pragma unroll
            for (int mt = 0; mt < 2; mt++)
                ldsm_x4(a[mt][0], a[mt][1], a[mt][2], a[mt][3],
                        sAl + (wm * 32 + mt * 16 + a_row) * ROWB + (kk + a_koff) * 2);
            #pragma unroll
            for (int mt = 0; mt < 2; mt++)
                #pragma unroll
                for (int np = 0; np < 4; np++) {
                    mma_bf16(acc[mt][2 * np],     a[mt][0], a[mt][1], a[mt][2], a[mt][3], b[np][0], b[np][1]);
                    mma_bf16(acc[mt][2 * np + 1], a[mt][0], a[mt][1], a[mt][2], a[mt][3], b[np][2], b[np][3]);
                }
            // --- pass 3: Ahi * Blo (reload a_hi, b_lo) ---
            #pragma unroll
            for (int mt = 0; mt < 2; mt++)
                ldsm_x4(a[mt][0], a[mt][1], a[mt][2], a[mt][3],
                        sA + (wm * 32 + mt * 16 + a_row) * ROWB + (kk + a_koff) * 2);
            #pragma unroll
            for (int np = 0; np < 4; np++)
                ldsm_x4(b[np][0], b[np][1], b[np][2], b[np][3],
                        sBl + (wn * 64 + np * 16 + b_nrow) * ROWB + (kk + b_koff) * 2);
            #pragma unroll
            for (int mt = 0; mt < 2; mt++)
                #pragma unroll
                for (int np = 0; np < 4; np++) {
                    mma_bf16(acc[mt][2 * np],     a[mt][0], a[mt][1], a[mt][2], a[mt][3], b[np][0], b[np][1]);
                    mma_bf16(acc[mt][2 * np + 1], a[mt][0], a[mt][1], a[mt][2], a[mt][3], b[np][2], b[np][3]);
                }
        }
        __syncthreads();   // before stage reuse by prefetch next iter
    }

    // Epilogue: acc[mt][nt]: c0,c1 -> row g, cols j,j+1; c2,c3 -> row g+8
    const int g = lane >> 2;
    const int cj = (lane & 3) * 2;
    #pragma unroll
    for (int mt = 0; mt < 2; mt++) {
        #pragma unroll
        for (int nt = 0; nt < 8; nt++) {
            const int row = row0 + wm * 32 + mt * 16 + g;
            const int col = col0 + wn * 64 + nt * 8 + cj;
            float2 v0, v1;
            v0.x = acc[mt][nt][0] + bias[col];
            v0.y = acc[mt][nt][1] + bias[col + 1];
            v1.x = acc[mt][nt][2] + bias[col];
            v1.y = acc[mt][nt][3] + bias[col + 1];
            *(float2*)&out[(size_t)row * N_ + col] = v0;
            *(float2*)&out[(size_t)(row + 8) * N_ + col] = v1;
        }
    }
}

// ---------------------------------------------------------------------------
// Flash-attention-style causal attention, fp32 (unchanged, measured 591us).
// ---------------------------------------------------------------------------
#define BR 64
#define BC 64

__global__ __launch_bounds__(256)
void attn_kernel(const float* __restrict__ Q,
                 const float* __restrict__ K,
                 const float* __restrict__ V,
                 float* __restrict__ Y)
{
    extern __shared__ float smf[];
    float* Qs = smf;                      // [64][64]
    float* Ks = smf + 64 * 64;            // [64][65]  (reused for P)
    float* Vs = smf + 64 * 64 + 64 * 65;  // [64][64]
#define QS(r, d) Qs[(r) * 64 + (d)]
#define KS(r, d) Ks[(r) * 65 + (d)]
#define VS(r, d) Vs[(r) * 64 + (d)]

    const int qt = blockIdx.x;
    const int h  = blockIdx.y;
    const int b  = blockIdx.z;
    const int t  = threadIdx.x;
    const int tx = t & 15;
    const int ty = t >> 4;
    const float scale = 0.125f;  // 1/sqrt(64)

    const size_t base = (size_t)b * T_ * C_ + (size_t)h * HD_;

    for (int i = t; i < BR * HD_; i += 256) {
        const int r = i >> 6, d = i & 63;
        QS(r, d) = Q[base + (size_t)(qt * BR + r) * C_ + d];
    }

    float acc[4][4] = {};
    float m_i[4], l_i[4];
    #pragma unroll
    for (int i = 0; i < 4; i++) { m_i[i] = -1e30f; l_i[i] = 0.f; }

    for (int kt = 0; kt <= qt; kt++) {
        for (int i = t; i < BC * HD_; i += 256) {
            const int r = i >> 6, d = i & 63;
            KS(r, d) = K[base + (size_t)(kt * BC + r) * C_ + d];
            VS(r, d) = V[base + (size_t)(kt * BC + r) * C_ + d];
        }
        __syncthreads();

        float s[4][4] = {};
        #pragma unroll
        for (int d = 0; d < HD_; d++) {
            float a[4], kk[4];
            #pragma unroll
            for (int i = 0; i < 4; i++) a[i]  = QS(ty * 4 + i, d);
            #pragma unroll
            for (int j = 0; j < 4; j++) kk[j] = KS(tx * 4 + j, d);
            #pragma unroll
            for (int i = 0; i < 4; i++)
                #pragma unroll
                for (int j = 0; j < 4; j++)
                    s[i][j] += a[i] * kk[j];
        }

        #pragma unroll
        for (int i = 0; i < 4; i++)
            #pragma unroll
            for (int j = 0; j < 4; j++) {
                s[i][j] *= scale;
                if (kt == qt && (tx * 4 + j) > (ty * 4 + i)) s[i][j] = -1e30f;
            }

        float p[4][4];
        #pragma unroll
        for (int i = 0; i < 4; i++) {
            float mx = s[i][0];
            #pragma unroll
            for (int j = 1; j < 4; j++) mx = fmaxf(mx, s[i][j]);
            #pragma unroll
            for (int off = 8; off >= 1; off >>= 1)
                mx = fmaxf(mx, __shfl_xor_sync(0xffffffffu, mx, off, 16));
            const float mnew = fmaxf(m_i[i], mx);

            float rs = 0.f;
            #pragma unroll
            for (int j = 0; j < 4; j++) {
                p[i][j] = __expf(s[i][j] - mnew);
                rs += p[i][j];
            }
            #pragma unroll
            for (int off = 8; off >= 1; off >>= 1)
                rs += __shfl_xor_sync(0xffffffffu, rs, off, 16);

            const float corr = __expf(m_i[i] - mnew);
            l_i[i] = l_i[i] * corr + rs;
            m_i[i] = mnew;
            #pragma unroll
            for (int dj = 0; dj < 4; dj++) acc[i][dj] *= corr;
        }

        __syncthreads();
        #pragma unroll
        for (int i = 0; i < 4; i++)
            #pragma unroll
            for (int j = 0; j < 4; j++)
                KS(ty * 4 + i, tx * 4 + j) = p[i][j];
        __syncthreads();

        #pragma unroll
        for (int j = 0; j < BC; j++) {
            float pv[4], vv[4];
            #pragma unroll
            for (int i = 0; i < 4; i++)   pv[i]  = KS(ty * 4 + i, j);
            #pragma unroll
            for (int dj = 0; dj < 4; dj++) vv[dj] = VS(j, tx * 4 + dj);
            #pragma unroll
            for (int i = 0; i < 4; i++)
                #pragma unroll
                for (int dj = 0; dj < 4; dj++)
                    acc[i][dj] += pv[i] * vv[dj];
        }
        __syncthreads();
    }

    #pragma unroll
    for (int i = 0; i < 4; i++) {
        const float inv = 1.f / l_i[i];
        const int qrow = qt * BR + ty * 4 + i;
        #pragma unroll
        for (int dj = 0; dj < 4; dj++)
            Y[base + (size_t)qrow * C_ + tx * 4 + dj] = acc[i][dj] * inv;
    }
#undef QS
#undef KS
#undef VS
}

// ---------------------------------------------------------------------------
// Launch
// ---------------------------------------------------------------------------
extern "C" void kernel_launch(void* const* d_in, const int* in_sizes, int n_in,
                              void* d_out, int out_size)
{
    const float* query = (const float*)d_in[0];
    const float* key_  = (const float*)d_in[1];
    const float* value = (const float*)d_in[2];
    // d_in[3] = att_mask (constant tril) — causal masking handled analytically
    const float* Wq = (const float*)d_in[4];
    const float* bq = (const float*)d_in[5];
    const float* Wk = (const float*)d_in[6];
    const float* bk = (const float*)d_in[7];
    const float* Wv = (const float*)d_in[8];
    const float* bv = (const float*)d_in[9];
    const float* Wp = (const float*)d_in[10];
    const float* bp = (const float*)d_in[11];
    float* out = (float*)d_out;

    float *Qb, *Kb, *Vb, *Yb;
    __nv_bfloat16 *Ahi, *Alo, *Bhi, *Blo;
    cudaGetSymbolAddress((void**)&Qb, g_Q);
    cudaGetSymbolAddress((void**)&Kb, g_K);
    cudaGetSymbolAddress((void**)&Vb, g_V);
    cudaGetSymbolAddress((void**)&Yb, g_Y);
    cudaGetSymbolAddress((void**)&Ahi, g_Ahi);
    cudaGetSymbolAddress((void**)&Alo, g_Alo);
    cudaGetSymbolAddress((void**)&Bhi, g_Bhi);
    cudaGetSymbolAddress((void**)&Blo, g_Blo);

    cudaFuncSetAttribute(gemm_mma_kernel, cudaFuncAttributeMaxDynamicSharedMemorySize, SMEM_GEMM);

    const dim3 ggrid(N_ / 128, M_ / 128);        // 8 x 32 = 256 CTAs
    const dim3 sxgrid(M_ * K_ / 4 / 256);        // splitX: 1 float4/thread
    const dim3 wtgrid(N_ / 32, K_ / 32);         // splitWT
    const dim3 wtblk(32, 8);

    // Q = query @ Wq + bq
    splitX_kernel <<<sxgrid, 256>>>(query, Ahi, Alo);
    splitWT_kernel<<<wtgrid, wtblk>>>(Wq, Bhi, Blo);
    gemm_mma_kernel<<<ggrid, 256, SMEM_GEMM>>>(Ahi, Alo, Bhi, Blo, bq, Qb);

    // K = key @ Wk + bk
    splitX_kernel <<<sxgrid, 256>>>(key_, Ahi, Alo);
    splitWT_kernel<<<wtgrid, wtblk>>>(Wk, Bhi, Blo);
    gemm_mma_kernel<<<ggrid, 256, SMEM_GEMM>>>(Ahi, Alo, Bhi, Blo, bk, Kb);

    // V = value @ Wv + bv
    splitX_kernel <<<sxgrid, 256>>>(value, Ahi, Alo);
    splitWT_kernel<<<wtgrid, wtblk>>>(Wv, Bhi, Blo);
    gemm_mma_kernel<<<ggrid, 256, SMEM_GEMM>>>(Ahi, Alo, Bhi, Blo, bv, Vb);

    // Attention (fp32)
    const int attn_smem = (64 * 64 + 64 * 65 + 64 * 64) * (int)sizeof(float);
    cudaFuncSetAttribute(attn_kernel, cudaFuncAttributeMaxDynamicSharedMemorySize, attn_smem);
    const dim3 agrid(T_ / BR, H_, B_);
    attn_kernel<<<agrid, 256, attn_smem>>>(Qb, Kb, Vb, Yb);

    // out = Y @ Wp + bp
    splitX_kernel <<<sxgrid, 256>>>(Yb, Ahi, Alo);
    splitWT_kernel<<<wtgrid, wtblk>>>(Wp, Bhi, Blo);
    gemm_mma_kernel<<<ggrid, 256, SMEM_GEMM>>>(Ahi, Alo, Bhi, Blo, bp, out);
}